// round 1
// baseline (speedup 1.0000x reference)
#include <cuda_runtime.h>
#include <cuda_bf16.h>

// Problem constants (fixed by the dataset's setup_inputs)
#define BS   8
#define CH   256
#define TLEN 512
#define PBIN 16
#define SRAT 4

// 4 MB transposed-input scratch: (b, t, c) layout so channel gathers coalesce.
__device__ float g_tr[BS * TLEN * CH];

// ---------------------------------------------------------------------------
// Kernel 1: transpose (b, ch, t) -> (b, t, ch), tiled 32x32 through smem.
// ---------------------------------------------------------------------------
__global__ void transpose_kernel(const float* __restrict__ in) {
    __shared__ float tile[32][33];
    const int b  = blockIdx.z;
    const int t0 = blockIdx.x * 32;
    const int c0 = blockIdx.y * 32;
    const int tx = threadIdx.x;          // 0..31
    const int ty = threadIdx.y;          // 0..7

    const float* inb  = in   + (size_t)b * CH * TLEN;
    float*       outb = g_tr + (size_t)b * TLEN * CH;

    #pragma unroll
    for (int j = 0; j < 32; j += 8)
        tile[ty + j][tx] = inb[(size_t)(c0 + ty + j) * TLEN + (t0 + tx)];
    __syncthreads();
    #pragma unroll
    for (int j = 0; j < 32; j += 8)
        outb[(size_t)(t0 + ty + j) * CH + (c0 + tx)] = tile[tx][ty + j];
}

// ---------------------------------------------------------------------------
// Kernel 2: one block per ROI. 256 threads = one thread per channel.
//   Phase A: threads 0..63 compute the 64 (p,s) sample positions + weights.
//   Phase B: thread c accumulates all 16 bins; gathers are 128B-coalesced
//            across the warp and identical across warps (L1-friendly).
//   Phase C: stage in smem (pad 17), write out linearly -> coalesced stores.
// ---------------------------------------------------------------------------
__global__ void roialign_kernel(const float* __restrict__ rois,
                                float* __restrict__ out) {
    const int n = blockIdx.x;
    const int c = threadIdx.x;           // channel

    __shared__ int   s_xlo[PBIN * SRAT];
    __shared__ int   s_xhi[PBIN * SRAT];
    __shared__ float s_wlo[PBIN * SRAT];
    __shared__ float s_whi[PBIN * SRAT];
    __shared__ int   s_b;
    __shared__ float s_out[CH * 17];     // [c][p] padded to 17 -> conflict-free STS

    if (c < PBIN * SRAT) {
        const float bf    = rois[n * 3 + 0];
        const float start = rois[n * 3 + 1];
        const float end   = rois[n * 3 + 2];
        if (c == 0) s_b = (int)bf;

        const float roi_len = fmaxf(end - start, 1.0f);
        const float bin     = roi_len * (1.0f / (float)PBIN);
        const int p = c >> 2;            // bin index
        const int s = c & 3;             // sample index
        const float x = start + ((float)p + ((float)s + 0.5f) * (1.0f / (float)SRAT)) * bin;
        const bool valid = (x >= -1.0f) && (x <= (float)TLEN);
        const float xc = fminf(fmaxf(x, 0.0f), (float)(TLEN - 1));
        const int xl = (int)floorf(xc);
        const int xh = min(xl + 1, TLEN - 1);
        const float lx = xc - (float)xl;
        s_xlo[c] = xl;
        s_xhi[c] = xh;
        s_wlo[c] = valid ? (1.0f - lx) : 0.0f;
        s_whi[c] = valid ? lx : 0.0f;
    }
    __syncthreads();

    const float* base = g_tr + (size_t)s_b * TLEN * CH;

    #pragma unroll
    for (int p = 0; p < PBIN; p++) {
        float acc = 0.0f;
        #pragma unroll
        for (int s = 0; s < SRAT; s++) {
            const int i = p * SRAT + s;
            acc += base[(size_t)s_xlo[i] * CH + c] * s_wlo[i];
            acc += base[(size_t)s_xhi[i] * CH + c] * s_whi[i];
        }
        s_out[c * 17 + p] = acc * (1.0f / (float)SRAT);
    }
    __syncthreads();

    // Coalesced writeback: out[n][c][p], linear index idx = c*16 + p.
    float* outn = out + (size_t)n * CH * PBIN;
    #pragma unroll
    for (int i = 0; i < PBIN; i++) {
        const int idx = c + CH * i;
        outn[idx] = s_out[(idx >> 4) * 17 + (idx & 15)];
    }
}

extern "C" void kernel_launch(void* const* d_in, const int* in_sizes, int n_in,
                              void* d_out, int out_size) {
    const float* input = (const float*)d_in[0];
    const float* rois  = (const float*)d_in[1];
    float*       out   = (float*)d_out;

    const int N = in_sizes[1] / 3;       // 2048 ROIs

    dim3 tgrid(TLEN / 32, CH / 32, BS);  // (16, 8, 8)
    dim3 tblk(32, 8);
    transpose_kernel<<<tgrid, tblk>>>(input);

    roialign_kernel<<<N, CH>>>(rois, out);
}

// round 2
// speedup vs baseline: 1.1691x; 1.1691x over previous
#include <cuda_runtime.h>
#include <cuda_bf16.h>

#define BS   8
#define CH   256
#define TLEN 512
#define PBIN 16
#define SRAT 4

// 4 MB transposed-input scratch: (b, t, c) layout so channel gathers coalesce.
__device__ float g_tr[BS * TLEN * CH];

// ---------------------------------------------------------------------------
// Kernel 1: transpose (b, ch, t) -> (b, t, ch), tiled 32x32 through smem.
// ---------------------------------------------------------------------------
__global__ void transpose_kernel(const float* __restrict__ in) {
    __shared__ float tile[32][33];
    const int b  = blockIdx.z;
    const int t0 = blockIdx.x * 32;
    const int c0 = blockIdx.y * 32;
    const int tx = threadIdx.x;          // 0..31
    const int ty = threadIdx.y;          // 0..7

    const float* inb  = in   + (size_t)b * CH * TLEN;
    float*       outb = g_tr + (size_t)b * TLEN * CH;

    #pragma unroll
    for (int j = 0; j < 32; j += 8)
        tile[ty + j][tx] = inb[(size_t)(c0 + ty + j) * TLEN + (t0 + tx)];
    __syncthreads();
    #pragma unroll
    for (int j = 0; j < 32; j += 8)
        outb[(size_t)(t0 + ty + j) * CH + (c0 + tx)] = tile[tx][ty + j];
}

// ---------------------------------------------------------------------------
// Kernel 2: one 64-thread block per ROI; thread owns 4 consecutive channels.
//   Phase A: thread i builds sample descriptor i (byte offsets + weights),
//            one uint4 in smem -> 1 broadcast LDS.128 per sample later.
//   Phase B: float4 gathers (LDG.128, warp-contiguous 512B), fma into float4
//            acc, STS.128 into a per-bin-rotated staging row.
//   Phase C: fully coalesced float4 writeback (q = lane + 64k), gathering the
//            4 words per output float4 from 4 staged bin-rows (<=2-way bank
//            conflict thanks to the p+(p>>2) rotation).
// ---------------------------------------------------------------------------
__global__ __launch_bounds__(64) void roialign_kernel(const float* __restrict__ rois,
                                                      float4* __restrict__ out) {
    const int n = blockIdx.x;
    const int l = threadIdx.x;           // 0..63

    __shared__ uint4  s_desc[PBIN * SRAT];      // 64 sample descriptors
    __shared__ float4 s_stage[PBIN * 64];       // [p][rotated float4-col]

    // ---- Phase A: per-sample descriptors (thread i == sample i) ----
    {
        const float bf    = __ldg(&rois[n * 3 + 0]);
        const float start = __ldg(&rois[n * 3 + 1]);
        const float end   = __ldg(&rois[n * 3 + 2]);
        const float roi_len = fmaxf(end - start, 1.0f);
        const float bin     = roi_len * (1.0f / (float)PBIN);

        const int p = l >> 2;            // bin
        const int s = l & 3;             // sample
        const float x = start + ((float)p + ((float)s + 0.5f) * 0.25f) * bin;
        const bool valid = (x >= -1.0f) && (x <= (float)TLEN);
        const float xc = fminf(fmaxf(x, 0.0f), (float)(TLEN - 1));
        const int xl = (int)floorf(xc);
        const int xh = min(xl + 1, TLEN - 1);
        const float lx = xc - (float)xl;
        const int b = (int)bf;

        uint4 d;
        d.x = (unsigned)(((b << 9) + xl) << 10);   // byte offset of row xl
        d.y = (unsigned)(((b << 9) + xh) << 10);   // byte offset of row xh
        d.z = __float_as_uint(valid ? (1.0f - lx) : 0.0f);
        d.w = __float_as_uint(valid ? lx : 0.0f);
        s_desc[l] = d;
    }
    __syncthreads();

    // ---- Phase B: gather + accumulate (4 channels per thread) ----
    const char* base = (const char*)g_tr + l * 16;   // this thread's channel group

    #pragma unroll 2
    for (int p = 0; p < PBIN; p++) {
        float4 acc = make_float4(0.0f, 0.0f, 0.0f, 0.0f);
        #pragma unroll
        for (int s = 0; s < SRAT; s++) {
            const uint4 d = s_desc[p * SRAT + s];
            const float4 vlo = *(const float4*)(base + d.x);
            const float4 vhi = *(const float4*)(base + d.y);
            const float wlo = __uint_as_float(d.z);
            const float whi = __uint_as_float(d.w);
            acc.x += vlo.x * wlo + vhi.x * whi;
            acc.y += vlo.y * wlo + vhi.y * whi;
            acc.z += vlo.z * wlo + vhi.z * whi;
            acc.w += vlo.w * wlo + vhi.w * whi;
        }
        acc.x *= 0.25f; acc.y *= 0.25f; acc.z *= 0.25f; acc.w *= 0.25f;
        // rotated store: rotation p + (p>>2) makes read-side banks distinct
        s_stage[p * 64 + ((l + p + (p >> 2)) & 63)] = acc;
    }
    __syncthreads();

    // ---- Phase C: coalesced writeback ----
    float4* outn = out + (size_t)n * (CH * PBIN / 4);
    const float* st = (const float*)s_stage;

    #pragma unroll
    for (int k = 0; k < 16; k++) {
        const int q = l + 64 * k;        // output float4 index (coalesced)
        const int c = q >> 2;            // channel
        const int g = q & 3;             // p-group
        const int t = c >> 2;            // staged float4 column (pre-rotation)
        const int j = c & 3;             // component within staged float4
        const int p0 = 4 * g;
        float4 v;
        v.x = st[(p0 + 0) * 256 + 4 * ((t + (p0 + 0) + ((p0 + 0) >> 2)) & 63) + j];
        v.y = st[(p0 + 1) * 256 + 4 * ((t + (p0 + 1) + ((p0 + 1) >> 2)) & 63) + j];
        v.z = st[(p0 + 2) * 256 + 4 * ((t + (p0 + 2) + ((p0 + 2) >> 2)) & 63) + j];
        v.w = st[(p0 + 3) * 256 + 4 * ((t + (p0 + 3) + ((p0 + 3) >> 2)) & 63) + j];
        outn[q] = v;
    }
}

extern "C" void kernel_launch(void* const* d_in, const int* in_sizes, int n_in,
                              void* d_out, int out_size) {
    const float* input = (const float*)d_in[0];
    const float* rois  = (const float*)d_in[1];
    float4*      out   = (float4*)d_out;

    const int N = in_sizes[1] / 3;       // 2048 ROIs

    dim3 tgrid(TLEN / 32, CH / 32, BS);  // (16, 8, 8)
    dim3 tblk(32, 8);
    transpose_kernel<<<tgrid, tblk>>>(input);

    roialign_kernel<<<N, 64>>>(rois, out);
}